// round 1
// baseline (speedup 1.0000x reference)
#include <cuda_runtime.h>
#include <math.h>

#define N_NODES 50000
#define N_EDGES 800000
#define N_REL 8
#define HID 128
#define OUT_CH 64
#define IN_CH 128

// ---------------- scratch (static device globals; no allocation) ----------------
__device__ float g_h [N_NODES * HID];          // 25.6 MB
__device__ float g_h2[N_NODES * HID];          // 25.6 MB
__device__ float g_Y [(size_t)N_NODES * 1024]; // 204.8 MB  (x_all, [n][r][c])
__device__ float g_Wcat[128 * 1024];           // repacked weights [i][r*128+o]
__device__ float g_qw[N_REL * 128];
__device__ float g_kw[N_REL * 128];
__device__ float g_sq[N_NODES * N_REL];
__device__ float g_sk[N_NODES * N_REL];
__device__ float g_alpha[N_EDGES];             // sorted by dst
__device__ int   g_yidx [N_EDGES];             // src*1024 + rel*128, sorted by dst
__device__ int   g_deg [N_NODES];
__device__ int   g_off [N_NODES + 1];
__device__ int   g_cur [N_NODES];
__device__ int   g_perm[N_EDGES];

// ---------------- CSR build ----------------
__global__ void zero_counts_kernel() {
    int t = blockIdx.x * blockDim.x + threadIdx.x;
    if (t < N_NODES) { g_deg[t] = 0; g_cur[t] = 0; }
}

__global__ void hist_kernel(const int* __restrict__ dst) {
    int e = blockIdx.x * blockDim.x + threadIdx.x;
    if (e < N_EDGES) atomicAdd(&g_deg[dst[e]], 1);
}

__global__ void scan_kernel() {
    // single block, 1024 threads, exclusive scan of g_deg -> g_off
    const int T = 1024;
    const int per = (N_NODES + T - 1) / T;
    int t = threadIdx.x;
    int s0 = t * per;
    int s1 = min(s0 + per, N_NODES);
    int sum = 0;
    for (int i = s0; i < s1; ++i) sum += g_deg[i];
    __shared__ int ps[T];
    ps[t] = sum;
    __syncthreads();
    for (int d = 1; d < T; d <<= 1) {
        int v = (t >= d) ? ps[t - d] : 0;
        __syncthreads();
        ps[t] += v;
        __syncthreads();
    }
    int run = (t == 0) ? 0 : ps[t - 1];
    for (int i = s0; i < s1; ++i) { g_off[i] = run; run += g_deg[i]; }
    if (t == T - 1) g_off[N_NODES] = run;
}

__global__ void scatter_kernel(const int* __restrict__ dst) {
    int e = blockIdx.x * blockDim.x + threadIdx.x;
    if (e < N_EDGES) {
        int d = dst[e];
        int pos = g_off[d] + atomicAdd(&g_cur[d], 1);
        g_perm[pos] = e;
    }
}

// ---------------- h = z @ lin_w^T + lin_b ----------------
__global__ void lin_kernel(const float* __restrict__ z,
                           const float* __restrict__ W,
                           const float* __restrict__ b) {
    int t = blockIdx.x * blockDim.x + threadIdx.x;
    if (t >= N_NODES * HID) return;
    int n = t >> 7, c = t & 127;
    const float4* zr = (const float4*)(z + (size_t)n * OUT_CH);
    const float4* wr = (const float4*)(W + (size_t)c * OUT_CH);
    float acc = 0.f;
#pragma unroll
    for (int i = 0; i < OUT_CH / 4; ++i) {
        float4 a = zr[i], w4 = wr[i];
        acc += a.x * w4.x + a.y * w4.y + a.z * w4.z + a.w * w4.w;
    }
    g_h[t] = acc + b[c];
}

// ---------------- weight repack: Wcat[i][r*128+o] = w[r][i][o] ----------------
__global__ void repack_kernel(const float* __restrict__ w) {
    int t = blockIdx.x * blockDim.x + threadIdx.x;
    if (t >= 128 * 1024) return;
    int i = t >> 10;
    int r = (t >> 7) & 7;
    int o = t & 127;
    g_Wcat[t] = w[(((size_t)r * 128 + i) << 7) | o];
}

// ---------------- qw[r] = w[r] @ q ; kw[r] = w[r] @ k ----------------
__global__ void qk_kernel(const float* __restrict__ w,
                          const float* __restrict__ q,
                          const float* __restrict__ k) {
    int r = blockIdx.x >> 1;
    int isK = blockIdx.x & 1;
    int i = threadIdx.x;            // 0..127
    const float4* wr = (const float4*)(w + (((size_t)r * 128 + i) << 7));
    const float4* v  = (const float4*)(isK ? k : q);
    float acc = 0.f;
#pragma unroll
    for (int o = 0; o < 32; ++o) {
        float4 a = wr[o], b = v[o];
        acc += a.x * b.x + a.y * b.y + a.z * b.z + a.w * b.w;
    }
    if (isK) g_kw[r * 128 + i] = acc;
    else     g_qw[r * 128 + i] = acc;
}

// ---------------- per-node-per-rel logit halves ----------------
__global__ void s_kernel(int layer) {
    int t = blockIdx.x * blockDim.x + threadIdx.x;
    if (t >= N_NODES * 16) return;
    int n = t >> 4;
    int rw = t & 15;
    int r = rw >> 1;
    int isK = rw & 1;
    const float* hin = (layer == 0) ? g_h : g_h2;
    const float4* hv = (const float4*)(hin + (size_t)n * 128);
    const float4* wv = (const float4*)((isK ? g_kw : g_qw) + r * 128);
    float acc = 0.f;
#pragma unroll
    for (int i = 0; i < 32; ++i) {
        float4 a = hv[i], b = wv[i];
        acc += a.x * b.x + a.y * b.y + a.z * b.z + a.w * b.w;
    }
    if (isK) g_sk[n * 8 + r] = acc;
    else     g_sq[n * 8 + r] = acc;
}

// ---------------- big GEMM: Y[M,1024] = Hin[M,128] @ Wcat[128,1024] ----------------
__global__ __launch_bounds__(256) void gemm_kernel(int layer) {
    const float* __restrict__ A = (layer == 0) ? g_h : g_h2;
    __shared__ float As[32][68];   // padded, transposed tile [k][m]
    __shared__ float Bs[32][128];
    const int bm = blockIdx.x * 64;
    const int bn = blockIdx.y * 128;
    const int tid = threadIdx.x;
    const int tx = tid & 31;       // 32 col-groups of 4
    const int ty = tid >> 5;       // 8 row-groups of 8
    float acc[8][4];
#pragma unroll
    for (int i = 0; i < 8; ++i)
#pragma unroll
        for (int j = 0; j < 4; ++j) acc[i][j] = 0.f;

    for (int kk = 0; kk < 128; kk += 32) {
        // A tile: 64x32
#pragma unroll
        for (int l = 0; l < 2; ++l) {
            int s = tid + l * 256;
            int m = s >> 3;
            int k4 = s & 7;
            int gm = bm + m;
            float4 v = make_float4(0.f, 0.f, 0.f, 0.f);
            if (gm < N_NODES)
                v = *(const float4*)(A + (size_t)gm * 128 + kk + k4 * 4);
            As[k4 * 4 + 0][m] = v.x;
            As[k4 * 4 + 1][m] = v.y;
            As[k4 * 4 + 2][m] = v.z;
            As[k4 * 4 + 3][m] = v.w;
        }
        // B tile: 32x128
#pragma unroll
        for (int l = 0; l < 4; ++l) {
            int s = tid + l * 256;
            int k = s >> 5;
            int n4 = s & 31;
            *(float4*)&Bs[k][n4 * 4] =
                *(const float4*)(g_Wcat + (size_t)(kk + k) * 1024 + bn + n4 * 4);
        }
        __syncthreads();
#pragma unroll
        for (int k = 0; k < 32; ++k) {
            float4 a0 = *(const float4*)&As[k][ty * 8];
            float4 a1 = *(const float4*)&As[k][ty * 8 + 4];
            float4 b4 = *(const float4*)&Bs[k][tx * 4];
            float av[8] = {a0.x, a0.y, a0.z, a0.w, a1.x, a1.y, a1.z, a1.w};
            float bv[4] = {b4.x, b4.y, b4.z, b4.w};
#pragma unroll
            for (int i = 0; i < 8; ++i)
#pragma unroll
                for (int j = 0; j < 4; ++j) acc[i][j] += av[i] * bv[j];
        }
        __syncthreads();
    }
#pragma unroll
    for (int i = 0; i < 8; ++i) {
        int gm = bm + ty * 8 + i;
        if (gm < N_NODES)
            *(float4*)(g_Y + (size_t)gm * 1024 + bn + tx * 4) =
                make_float4(acc[i][0], acc[i][1], acc[i][2], acc[i][3]);
    }
}

// ---------------- edge logits (in dst-sorted order) ----------------
__global__ void alpha_kernel(const int* __restrict__ src,
                             const int* __restrict__ dst,
                             const int* __restrict__ et) {
    int j = blockIdx.x * blockDim.x + threadIdx.x;
    if (j >= N_EDGES) return;
    int e = g_perm[j];
    int sn = src[e], dn = dst[e], r = et[e];
    float a = g_sq[dn * 8 + r] + g_sk[sn * 8 + r];
    g_alpha[j] = (a > 0.f) ? a : 0.2f * a;
    g_yidx[j] = sn * 1024 + r * 128;
}

// ---------------- segment softmax + weighted aggregation ----------------
__global__ __launch_bounds__(128) void aggregate_kernel(const float* __restrict__ bias,
                                                        float* __restrict__ out_ext,
                                                        int layer) {
    int n = blockIdx.x;
    int c = threadIdx.x;               // 0..127
    float* outp = (layer == 0) ? g_h2 : out_ext;
    int s = g_off[n], e = g_off[n + 1];

    if (s == e) {
        float v = bias[c];
        if (layer == 0) v = fmaxf(v, 0.f);
        outp[(size_t)n * 128 + c] = v;
        return;
    }

    __shared__ float sh[128];
    __shared__ float exbuf[128];
    __shared__ int   idxbuf[128];

    // segment max
    float mx = -1e30f;
    for (int j = s + c; j < e; j += 128) mx = fmaxf(mx, g_alpha[j]);
    sh[c] = mx;
    __syncthreads();
#pragma unroll
    for (int d = 64; d > 0; d >>= 1) {
        if (c < d) sh[c] = fmaxf(sh[c], sh[c + d]);
        __syncthreads();
    }
    mx = sh[0];
    __syncthreads();

    float acc = 0.f, den = 0.f;
    for (int base = s; base < e; base += 128) {
        int j = base + c;
        if (j < e) {
            float ex = __expf(g_alpha[j] - mx);
            exbuf[c] = ex;
            idxbuf[c] = g_yidx[j];
            den += ex;
        }
        __syncthreads();
        int cnt = min(128, e - base);
#pragma unroll 4
        for (int t = 0; t < cnt; ++t) {
            acc += exbuf[t] * __ldg(&g_Y[(size_t)idxbuf[t] + c]);
        }
        __syncthreads();
    }

    sh[c] = den;
    __syncthreads();
#pragma unroll
    for (int d = 64; d > 0; d >>= 1) {
        if (c < d) sh[c] += sh[c + d];
        __syncthreads();
    }
    den = sh[0];

    float v = acc / (den + 1e-16f) + bias[c];
    if (layer == 0) v = fmaxf(v, 0.f);
    outp[(size_t)n * 128 + c] = v;
}

// ---------------- launch ----------------
extern "C" void kernel_launch(void* const* d_in, const int* in_sizes, int n_in,
                              void* d_out, int out_size) {
    const float* z     = (const float*)d_in[0];
    const float* lin_w = (const float*)d_in[1];
    const float* lin_b = (const float*)d_in[2];
    const float* w1    = (const float*)d_in[3];
    const float* q1    = (const float*)d_in[4];
    const float* k1    = (const float*)d_in[5];
    const float* b1    = (const float*)d_in[6];
    const float* w2    = (const float*)d_in[7];
    const float* q2    = (const float*)d_in[8];
    const float* k2    = (const float*)d_in[9];
    const float* b2    = (const float*)d_in[10];
    const int*   ei    = (const int*)d_in[11];
    const int*   et    = (const int*)d_in[12];
    const int* src = ei;
    const int* dst = ei + N_EDGES;
    float* out = (float*)d_out;

    const int EB = N_EDGES / 256;   // 3125 exact

    // CSR by dst (shared across both layers)
    zero_counts_kernel<<<(N_NODES + 511) / 512, 512>>>();
    hist_kernel<<<EB, 256>>>(dst);
    scan_kernel<<<1, 1024>>>();
    scatter_kernel<<<EB, 256>>>(dst);

    // encoder linear
    lin_kernel<<<(N_NODES * 128 + 255) / 256, 256>>>(z, lin_w, lin_b);

    dim3 ggrid((N_NODES + 63) / 64, 8);

    // ---- layer 1 ----
    repack_kernel<<<(128 * 1024) / 256, 256>>>(w1);
    qk_kernel<<<16, 128>>>(w1, q1, k1);
    s_kernel<<<(N_NODES * 16 + 255) / 256, 256>>>(0);
    gemm_kernel<<<ggrid, 256>>>(0);
    alpha_kernel<<<EB, 256>>>(src, dst, et);
    aggregate_kernel<<<N_NODES, 128>>>(b1, out, 0);   // writes g_h2 (relu)

    // ---- layer 2 ----
    repack_kernel<<<(128 * 1024) / 256, 256>>>(w2);
    qk_kernel<<<16, 128>>>(w2, q2, k2);
    s_kernel<<<(N_NODES * 16 + 255) / 256, 256>>>(1);
    gemm_kernel<<<ggrid, 256>>>(1);
    alpha_kernel<<<EB, 256>>>(src, dst, et);
    aggregate_kernel<<<N_NODES, 128>>>(b2, out, 1);   // writes d_out
}

// round 3
// speedup vs baseline: 1.2360x; 1.2360x over previous
#include <cuda_runtime.h>
#include <cuda_bf16.h>
#include <stdint.h>
#include <math.h>

#define N_NODES 50000
#define N_PAD   50048          // 391 * 128
#define N_EDGES 800000
#define N_REL 8
#define HID 128
#define OUT_CH 64

// ---------------- scratch (static device globals; no allocation) ----------------
__device__ __align__(16) float g_h [N_NODES * HID];                // 25.6 MB
__device__ __align__(16) float g_h2[N_NODES * HID];                // 25.6 MB
__device__ __align__(16) __nv_bfloat16 g_Zbf[(size_t)N_PAD * 2048]; // 205 MB (hi cols 0..1023 | lo 1024..2047)
__device__ __align__(16) __nv_bfloat16 g_Wbf[2048 * 128];           // 0.5 MB (hi rows 0..1023 | lo 1024..2047)
__device__ __align__(16) float g_qw[N_REL * 128];
__device__ __align__(16) float g_kw[N_REL * 128];
__device__ float g_sq[N_NODES * N_REL];
__device__ float g_sk[N_NODES * N_REL];
__device__ float g_alpha[N_EDGES];
__device__ int   g_yidx [N_EDGES];     // src*8 + rel, dst-sorted
__device__ int   g_deg [N_NODES];
__device__ int   g_off [N_NODES + 1];
__device__ int   g_cur [N_NODES];
__device__ int   g_perm[N_EDGES];

// ================= PTX helpers =================
__device__ __forceinline__ uint32_t smem_u32(const void* p) {
    uint32_t a;
    asm("{ .reg .u64 t; cvta.to.shared.u64 t, %1; cvt.u32.u64 %0, t; }" : "=r"(a) : "l"(p));
    return a;
}
#define CP16(dst, src) \
    asm volatile("cp.async.cg.shared.global [%0], [%1], 16;" :: "r"(dst), "l"(src))
#define CP_COMMIT() asm volatile("cp.async.commit_group;" ::: "memory")
#define CP_WAIT2()  asm volatile("cp.async.wait_group 2;" ::: "memory")

#define LDSM_X4(r, addr) \
    asm volatile("ldmatrix.sync.aligned.m8n8.x4.shared.b16 {%0,%1,%2,%3}, [%4];" \
        : "=r"((r)[0]), "=r"((r)[1]), "=r"((r)[2]), "=r"((r)[3]) : "r"(addr))
#define LDSM_X4_T(r0, r1, r2, r3, addr) \
    asm volatile("ldmatrix.sync.aligned.m8n8.x4.trans.shared.b16 {%0,%1,%2,%3}, [%4];" \
        : "=r"(r0), "=r"(r1), "=r"(r2), "=r"(r3) : "r"(addr))

#define MMA_BF16(d, a, b) \
    asm volatile("mma.sync.aligned.m16n8k16.row.col.f32.bf16.bf16.f32 " \
        "{%0,%1,%2,%3}, {%4,%5,%6,%7}, {%8,%9}, {%0,%1,%2,%3};" \
        : "+f"((d)[0]), "+f"((d)[1]), "+f"((d)[2]), "+f"((d)[3]) \
        : "r"((a)[0]), "r"((a)[1]), "r"((a)[2]), "r"((a)[3]), "r"((b)[0]), "r"((b)[1]))

__device__ __forceinline__ uint32_t sw128(uint32_t b) { return b ^ ((b >> 3) & 0x70); }

// smem stage layout: Ahi 16KB | Alo 16KB | Bhi 17408 | Blo 17408  = 67584 B, 3 stages
#define ST_ALO 16384
#define ST_BHI 32768
#define ST_BLO 50176
#define STAGE_BYTES 67584
#define GEMM_SMEM (3 * STAGE_BYTES)

// ---------------- CSR build ----------------
__global__ void zero_counts_kernel() {
    int t = blockIdx.x * blockDim.x + threadIdx.x;
    if (t < N_NODES) { g_deg[t] = 0; g_cur[t] = 0; }
}
__global__ void hist_kernel(const int* __restrict__ dst) {
    int e = blockIdx.x * blockDim.x + threadIdx.x;
    if (e < N_EDGES) atomicAdd(&g_deg[dst[e]], 1);
}
__global__ void scan_kernel() {
    const int T = 1024;
    const int per = (N_NODES + T - 1) / T;
    int t = threadIdx.x;
    int s0 = t * per, s1 = min(s0 + per, N_NODES);
    int sum = 0;
    for (int i = s0; i < s1; ++i) sum += g_deg[i];
    __shared__ int ps[T];
    ps[t] = sum; __syncthreads();
    for (int d = 1; d < T; d <<= 1) {
        int v = (t >= d) ? ps[t - d] : 0;
        __syncthreads(); ps[t] += v; __syncthreads();
    }
    int run = (t == 0) ? 0 : ps[t - 1];
    for (int i = s0; i < s1; ++i) { g_off[i] = run; run += g_deg[i]; }
    if (t == T - 1) g_off[N_NODES] = run;
}
__global__ void scatter_kernel(const int* __restrict__ dst) {
    int e = blockIdx.x * blockDim.x + threadIdx.x;
    if (e < N_EDGES) {
        int d = dst[e];
        int pos = g_off[d] + atomicAdd(&g_cur[d], 1);
        g_perm[pos] = e;
    }
}

// ---------------- h = z @ lin_w^T + lin_b ----------------
__global__ void lin_kernel(const float* __restrict__ z,
                           const float* __restrict__ W,
                           const float* __restrict__ b) {
    int t = blockIdx.x * blockDim.x + threadIdx.x;
    if (t >= N_NODES * HID) return;
    int n = t >> 7, c = t & 127;
    const float4* zr = (const float4*)(z + (size_t)n * OUT_CH);
    const float4* wr = (const float4*)(W + (size_t)c * OUT_CH);
    float acc = 0.f;
#pragma unroll
    for (int i = 0; i < OUT_CH / 4; ++i) {
        float4 a = zr[i], w4 = wr[i];
        acc += a.x * w4.x + a.y * w4.y + a.z * w4.z + a.w * w4.w;
    }
    g_h[t] = acc + b[c];
}

// ---------------- Wstack hi/lo split: g_Wbf[k][o], w is already [k=r*128+i][o] ----------------
__global__ void splitW_kernel(const float* __restrict__ w) {
    int t = blockIdx.x * blockDim.x + threadIdx.x;
    if (t >= 1024 * 128) return;
    float x = w[t];
    __nv_bfloat16 hi = __float2bfloat16(x);
    __nv_bfloat16 lo = __float2bfloat16(x - __bfloat162float(hi));
    g_Wbf[t] = hi;
    g_Wbf[1024 * 128 + t] = lo;
}

// ---------------- qw[r] = w[r] @ q ; kw[r] = w[r] @ k ----------------
__global__ void qk_kernel(const float* __restrict__ w,
                          const float* __restrict__ q,
                          const float* __restrict__ k) {
    int r = blockIdx.x >> 1;
    int isK = blockIdx.x & 1;
    int i = threadIdx.x;
    const float4* wr = (const float4*)(w + (((size_t)r * 128 + i) << 7));
    const float4* v  = (const float4*)(isK ? k : q);
    float acc = 0.f;
#pragma unroll
    for (int o = 0; o < 32; ++o) {
        float4 a = wr[o], b = v[o];
        acc += a.x * b.x + a.y * b.y + a.z * b.z + a.w * b.w;
    }
    if (isK) g_kw[r * 128 + i] = acc;
    else     g_qw[r * 128 + i] = acc;
}

// ---------------- per-node-per-rel logit halves (fp32 exact) ----------------
__global__ void s_kernel(int layer) {
    int t = blockIdx.x * blockDim.x + threadIdx.x;
    if (t >= N_NODES * 16) return;
    int n = t >> 4;
    int rw = t & 15;
    int r = rw >> 1;
    int isK = rw & 1;
    const float* hin = (layer == 0) ? g_h : g_h2;
    const float4* hv = (const float4*)(hin + (size_t)n * 128);
    const float4* wv = (const float4*)((isK ? g_kw : g_qw) + r * 128);
    float acc = 0.f;
#pragma unroll
    for (int i = 0; i < 32; ++i) {
        float4 a = hv[i], b = wv[i];
        acc += a.x * b.x + a.y * b.y + a.z * b.z + a.w * b.w;
    }
    if (isK) g_sk[n * 8 + r] = acc;
    else     g_sq[n * 8 + r] = acc;
}

// ---------------- edge logits (dst-sorted) ----------------
__global__ void alpha_kernel(const int* __restrict__ src,
                             const int* __restrict__ dst,
                             const int* __restrict__ et) {
    int j = blockIdx.x * blockDim.x + threadIdx.x;
    if (j >= N_EDGES) return;
    int e = g_perm[j];
    int sn = src[e], dn = dst[e], r = et[e];
    float a = g_sq[dn * 8 + r] + g_sk[sn * 8 + r];
    g_alpha[j] = (a > 0.f) ? a : 0.2f * a;
    g_yidx[j] = sn * 8 + r;
}

// ---------------- softmax + aggregate h into rel slots -> Zbf (bf16 hi/lo) ----------------
__global__ __launch_bounds__(128) void aggregate_kernel(int layer) {
    const float* __restrict__ hin = (layer == 0) ? g_h : g_h2;
    int n = blockIdx.x;
    int c = threadIdx.x;
    int s = g_off[n], e = g_off[n + 1];
    if (s == e) return;  // Zbf row stays zero (never written; zero-init)

    __shared__ float zrow[1024];
    __shared__ float exbuf[128];
    __shared__ int   ybuf[128];
    __shared__ float red[128];

#pragma unroll
    for (int b = 0; b < 8; ++b) zrow[b * 128 + c] = 0.f;

    // segment max
    float mx = -1e30f;
    for (int j = s + c; j < e; j += 128) mx = fmaxf(mx, g_alpha[j]);
    red[c] = mx;
    __syncthreads();
#pragma unroll
    for (int d = 64; d > 0; d >>= 1) {
        if (c < d) red[c] = fmaxf(red[c], red[c + d]);
        __syncthreads();
    }
    mx = red[0];
    __syncthreads();

    float den = 0.f;
    for (int base = s; base < e; base += 128) {
        int j = base + c;
        if (j < e) {
            float ex = __expf(g_alpha[j] - mx);
            exbuf[c] = ex;
            ybuf[c] = g_yidx[j];
            den += ex;
        }
        __syncthreads();
        int cnt = min(128, e - base);
        for (int t = 0; t < cnt; ++t) {
            int y = ybuf[t];
            zrow[(y & 7) * 128 + c] += exbuf[t] * __ldg(hin + (size_t)(y >> 3) * 128 + c);
        }
        __syncthreads();
    }

    red[c] = den;
    __syncthreads();
#pragma unroll
    for (int d = 64; d > 0; d >>= 1) {
        if (c < d) red[c] += red[c + d];
        __syncthreads();
    }
    float inv = 1.f / (red[0] + 1e-16f);

    __nv_bfloat16* zr = g_Zbf + (size_t)n * 2048;
#pragma unroll
    for (int b = 0; b < 8; ++b) {
        int k = b * 128 + c;
        float v = zrow[k] * inv;
        __nv_bfloat16 hi = __float2bfloat16(v);
        zr[k] = hi;
        zr[1024 + k] = __float2bfloat16(v - __bfloat162float(hi));
    }
}

// ================= mma.sync bf16 GEMM: out[M,128] = Z[M,1024] @ Wstack[1024,128] =================
__device__ __forceinline__ void stage_load(uint32_t st, int koff, int bm, int tid) {
#pragma unroll
    for (int it = 0; it < 4; ++it) {
        int i = tid + it * 256;
        int m = i >> 3, seg = i & 7;
        uint32_t sw = sw128((uint32_t)(m * 128 + seg * 16));
        const char* src = (const char*)(g_Zbf + (size_t)(bm + m) * 2048 + koff + seg * 8);
        CP16(st + sw, src);                          // A hi
        CP16(st + ST_ALO + sw, src + 2048);          // A lo (+1024 bf16)
    }
#pragma unroll
    for (int it = 0; it < 4; ++it) {
        int i = tid + it * 256;
        int k = i >> 4, nseg = i & 15;
        const char* src = (const char*)(g_Wbf + (size_t)(koff + k) * 128 + nseg * 8);
        CP16(st + ST_BHI + k * 272 + nseg * 16, src);
        CP16(st + ST_BLO + k * 272 + nseg * 16, src + 1024 * 128 * 2);
    }
}

__global__ __launch_bounds__(256, 1) void gemm_mma_kernel(float* __restrict__ out_ext,
                                                          const float* __restrict__ bias,
                                                          int relu, int to_h2) {
    extern __shared__ char sm[];
    uint32_t sb = smem_u32(sm);
    const int tid = threadIdx.x;
    const int wid = tid >> 5, lane = tid & 31;
    const int bm = blockIdx.x * 128;
    const int wm = wid & 3, wn = wid >> 2;

    float acc[2][8][4];
#pragma unroll
    for (int i = 0; i < 2; ++i)
#pragma unroll
        for (int j = 0; j < 8; ++j)
#pragma unroll
            for (int l = 0; l < 4; ++l) acc[i][j][l] = 0.f;

#pragma unroll
    for (int p = 0; p < 3; ++p) {
        stage_load(sb + p * STAGE_BYTES, p * 64, bm, tid);
        CP_COMMIT();
    }

    const int rA = lane & 15, cA = lane >> 4;
    const int rB8 = (lane & 7) + ((lane >> 3) & 1) * 8;
    const int nB = wn * 64 + (lane >> 4) * 8;

    for (int c = 0; c < 16; ++c) {
        CP_WAIT2();
        __syncthreads();
        uint32_t st = sb + (uint32_t)(c % 3) * STAGE_BYTES;

#pragma unroll
        for (int k16 = 0; k16 < 4; ++k16) {
            uint32_t aHi[2][4], aLo[2][4], bHi[8][2], bLo[8][2];
#pragma unroll
            for (int mt = 0; mt < 2; ++mt) {
                uint32_t sw = sw128((uint32_t)((wm * 32 + mt * 16 + rA) * 128 + k16 * 32 + cA * 16));
                LDSM_X4(aHi[mt], st + sw);
                LDSM_X4(aLo[mt], st + ST_ALO + sw);
            }
#pragma unroll
            for (int p = 0; p < 4; ++p) {
                uint32_t boff = (uint32_t)((k16 * 16 + rB8) * 272 + (nB + p * 16) * 2);
                LDSM_X4_T(bHi[2 * p][0], bHi[2 * p][1], bHi[2 * p + 1][0], bHi[2 * p + 1][1],
                          st + ST_BHI + boff);
                LDSM_X4_T(bLo[2 * p][0], bLo[2 * p][1], bLo[2 * p + 1][0], bLo[2 * p + 1][1],
                          st + ST_BLO + boff);
            }
#pragma unroll
            for (int mt = 0; mt < 2; ++mt)
#pragma unroll
                for (int nt = 0; nt < 8; ++nt) MMA_BF16(acc[mt][nt], aHi[mt], bHi[nt]);
#pragma unroll
            for (int mt = 0; mt < 2; ++mt)
#pragma unroll
                for (int nt = 0; nt < 8; ++nt) MMA_BF16(acc[mt][nt], aLo[mt], bHi[nt]);
#pragma unroll
            for (int mt = 0; mt < 2; ++mt)
#pragma unroll
                for (int nt = 0; nt < 8; ++nt) MMA_BF16(acc[mt][nt], aHi[mt], bLo[nt]);
        }
        __syncthreads();
        if (c + 3 < 16) stage_load(st, (c + 3) * 64, bm, tid);
        CP_COMMIT();   // possibly-empty group keeps pipeline bookkeeping uniform
    }

    float* __restrict__ outp = to_h2 ? g_h2 : out_ext;
    const int g = lane >> 2, t4 = lane & 3;
#pragma unroll
    for (int mt = 0; mt < 2; ++mt) {
        int row0 = bm + wm * 32 + mt * 16 + g;
        int row1 = row0 + 8;
#pragma unroll
        for (int nt = 0; nt < 8; ++nt) {
            int col = wn * 64 + nt * 8 + t4 * 2;
            float b0 = __ldg(bias + col), b1 = __ldg(bias + col + 1);
            float v00 = acc[mt][nt][0] + b0, v01 = acc[mt][nt][1] + b1;
            float v10 = acc[mt][nt][2] + b0, v11 = acc[mt][nt][3] + b1;
            if (relu) {
                v00 = fmaxf(v00, 0.f); v01 = fmaxf(v01, 0.f);
                v10 = fmaxf(v10, 0.f); v11 = fmaxf(v11, 0.f);
            }
            if (row0 < N_NODES) *(float2*)(outp + (size_t)row0 * 128 + col) = make_float2(v00, v01);
            if (row1 < N_NODES) *(float2*)(outp + (size_t)row1 * 128 + col) = make_float2(v10, v11);
        }
    }
}

// ---------------- launch ----------------
extern "C" void kernel_launch(void* const* d_in, const int* in_sizes, int n_in,
                              void* d_out, int out_size) {
    const float* z     = (const float*)d_in[0];
    const float* lin_w = (const float*)d_in[1];
    const float* lin_b = (const float*)d_in[2];
    const float* w1    = (const float*)d_in[3];
    const float* q1    = (const float*)d_in[4];
    const float* k1    = (const float*)d_in[5];
    const float* b1    = (const float*)d_in[6];
    const float* w2    = (const float*)d_in[7];
    const float* q2    = (const float*)d_in[8];
    const float* k2    = (const float*)d_in[9];
    const float* b2    = (const float*)d_in[10];
    const int*   ei    = (const int*)d_in[11];
    const int*   et    = (const int*)d_in[12];
    const int* src = ei;
    const int* dst = ei + N_EDGES;
    float* out = (float*)d_out;

    cudaFuncSetAttribute(gemm_mma_kernel, cudaFuncAttributeMaxDynamicSharedMemorySize, GEMM_SMEM);

    const int EB = N_EDGES / 256;   // 3125

    // shared prep
    lin_kernel<<<(N_NODES * 128) / 256, 256>>>(z, lin_w, lin_b);
    zero_counts_kernel<<<(N_NODES + 511) / 512, 512>>>();
    hist_kernel<<<EB, 256>>>(dst);
    scan_kernel<<<1, 1024>>>();
    scatter_kernel<<<EB, 256>>>(dst);

    // ---- layer 1 ----
    splitW_kernel<<<512, 256>>>(w1);
    qk_kernel<<<16, 128>>>(w1, q1, k1);
    s_kernel<<<(N_NODES * 16) / 256, 256>>>(0);
    alpha_kernel<<<EB, 256>>>(src, dst, et);
    aggregate_kernel<<<N_NODES, 128>>>(0);
    gemm_mma_kernel<<<N_PAD / 128, 256, GEMM_SMEM>>>(out, b1, 1, 1);  // -> g_h2 (relu)

    // ---- layer 2 ----
    splitW_kernel<<<512, 256>>>(w2);
    qk_kernel<<<16, 128>>>(w2, q2, k2);
    s_kernel<<<(N_NODES * 16) / 256, 256>>>(1);
    alpha_kernel<<<EB, 256>>>(src, dst, et);
    aggregate_kernel<<<N_NODES, 128>>>(1);
    gemm_mma_kernel<<<N_PAD / 128, 256, GEMM_SMEM>>>(out, b2, 0, 0);  // -> d_out
}

// round 4
// speedup vs baseline: 1.5539x; 1.2572x over previous
#include <cuda_runtime.h>
#include <cuda_bf16.h>
#include <stdint.h>
#include <math.h>

#define N_NODES 50000
#define N_PAD   50048          // 391 * 128
#define N_EDGES 800000
#define N_REL 8
#define HID 128
#define OUT_CH 64
#define NBIN (N_NODES * N_REL) // 400000
#define SCAN_NB 391            // ceil(400000/1024)

// ---------------- scratch (static device globals; no allocation) ----------------
__device__ __align__(16) float g_h [N_NODES * HID];
__device__ __align__(16) float g_h2[N_NODES * HID];
__device__ __align__(16) __nv_bfloat16 g_Zbf[(size_t)N_PAD * 2048]; // hi cols 0..1023 | lo 1024..2047
__device__ __align__(16) __nv_bfloat16 g_Wbf[2048 * 128];
__device__ __align__(16) float g_qw[N_REL * 128];
__device__ __align__(16) float g_kw[N_REL * 128];
__device__ float g_sq[N_NODES * N_REL];
__device__ float g_sk[N_NODES * N_REL];
__device__ float g_alpha[N_EDGES];     // sorted by (dst, rel)
__device__ int   g_srcs [N_EDGES];     // src node, sorted
__device__ int   g_dr   [N_EDGES];     // dst*8+rel, sorted
__device__ int   g_deg8[NBIN];
__device__ int   g_cur8[NBIN];
__device__ int   g_off8[NBIN + 1];
__device__ int   g_bsum[SCAN_NB];
__device__ int   g_boff[SCAN_NB];

// ================= PTX helpers =================
__device__ __forceinline__ uint32_t smem_u32(const void* p) {
    uint32_t a;
    asm("{ .reg .u64 t; cvta.to.shared.u64 t, %1; cvt.u32.u64 %0, t; }" : "=r"(a) : "l"(p));
    return a;
}
#define CP16(dst, src) \
    asm volatile("cp.async.cg.shared.global [%0], [%1], 16;" :: "r"(dst), "l"(src))
#define CP_COMMIT() asm volatile("cp.async.commit_group;" ::: "memory")
#define CP_WAIT2()  asm volatile("cp.async.wait_group 2;" ::: "memory")

#define LDSM_X4(r, addr) \
    asm volatile("ldmatrix.sync.aligned.m8n8.x4.shared.b16 {%0,%1,%2,%3}, [%4];" \
        : "=r"((r)[0]), "=r"((r)[1]), "=r"((r)[2]), "=r"((r)[3]) : "r"(addr))
#define LDSM_X4_T(r0, r1, r2, r3, addr) \
    asm volatile("ldmatrix.sync.aligned.m8n8.x4.trans.shared.b16 {%0,%1,%2,%3}, [%4];" \
        : "=r"(r0), "=r"(r1), "=r"(r2), "=r"(r3) : "r"(addr))

#define MMA_BF16(d, a, b) \
    asm volatile("mma.sync.aligned.m16n8k16.row.col.f32.bf16.bf16.f32 " \
        "{%0,%1,%2,%3}, {%4,%5,%6,%7}, {%8,%9}, {%0,%1,%2,%3};" \
        : "+f"((d)[0]), "+f"((d)[1]), "+f"((d)[2]), "+f"((d)[3]) \
        : "r"((a)[0]), "r"((a)[1]), "r"((a)[2]), "r"((a)[3]), "r"((b)[0]), "r"((b)[1]))

__device__ __forceinline__ uint32_t sw128(uint32_t b) { return b ^ ((b >> 3) & 0x70); }

#define ST_ALO 16384
#define ST_BHI 32768
#define ST_BLO 50176
#define STAGE_BYTES 67584
#define GEMM_SMEM (3 * STAGE_BYTES)

// ---------------- CSR build (binned by dst*8+rel) ----------------
__global__ void zero8_kernel() {
    int t = blockIdx.x * blockDim.x + threadIdx.x;
    if (t < NBIN) { g_deg8[t] = 0; g_cur8[t] = 0; }
}
__global__ void hist8_kernel(const int* __restrict__ dst, const int* __restrict__ et) {
    int e = blockIdx.x * blockDim.x + threadIdx.x;
    if (e < N_EDGES) atomicAdd(&g_deg8[dst[e] * 8 + et[e]], 1);
}
__global__ __launch_bounds__(1024) void scan1_kernel() {
    __shared__ int sh[1024];
    int b = blockIdx.x, t = threadIdx.x;
    int i = b * 1024 + t;
    int v = (i < NBIN) ? g_deg8[i] : 0;
    sh[t] = v; __syncthreads();
#pragma unroll
    for (int d = 1; d < 1024; d <<= 1) {
        int x = (t >= d) ? sh[t - d] : 0;
        __syncthreads(); sh[t] += x; __syncthreads();
    }
    if (i < NBIN) g_off8[i] = sh[t] - v;   // exclusive
    if (t == 1023) g_bsum[b] = sh[1023];
}
__global__ __launch_bounds__(512) void scan2_kernel() {
    __shared__ int sh[512];
    int t = threadIdx.x;
    int v = (t < SCAN_NB) ? g_bsum[t] : 0;
    sh[t] = v; __syncthreads();
#pragma unroll
    for (int d = 1; d < 512; d <<= 1) {
        int x = (t >= d) ? sh[t - d] : 0;
        __syncthreads(); sh[t] += x; __syncthreads();
    }
    if (t < SCAN_NB) g_boff[t] = sh[t] - v;
    if (t == SCAN_NB - 1) g_off8[NBIN] = sh[t];
}
__global__ __launch_bounds__(1024) void scan3_kernel() {
    int i = blockIdx.x * 1024 + threadIdx.x;
    if (i < NBIN) g_off8[i] += g_boff[blockIdx.x];
}
__global__ void scatter_kernel(const int* __restrict__ src,
                               const int* __restrict__ dst,
                               const int* __restrict__ et) {
    int e = blockIdx.x * blockDim.x + threadIdx.x;
    if (e >= N_EDGES) return;
    int key = dst[e] * 8 + et[e];
    int pos = g_off8[key] + atomicAdd(&g_cur8[key], 1);
    g_srcs[pos] = src[e];
    g_dr[pos] = key;
}

// ---------------- h = z @ lin_w^T + lin_b ----------------
__global__ void lin_kernel(const float* __restrict__ z,
                           const float* __restrict__ W,
                           const float* __restrict__ b) {
    int t = blockIdx.x * blockDim.x + threadIdx.x;
    if (t >= N_NODES * HID) return;
    int n = t >> 7, c = t & 127;
    const float4* zr = (const float4*)(z + (size_t)n * OUT_CH);
    const float4* wr = (const float4*)(W + (size_t)c * OUT_CH);
    float acc = 0.f;
#pragma unroll
    for (int i = 0; i < OUT_CH / 4; ++i) {
        float4 a = zr[i], w4 = wr[i];
        acc += a.x * w4.x + a.y * w4.y + a.z * w4.z + a.w * w4.w;
    }
    g_h[t] = acc + b[c];
}

// ---------------- Wstack hi/lo split ----------------
__global__ void splitW_kernel(const float* __restrict__ w) {
    int t = blockIdx.x * blockDim.x + threadIdx.x;
    if (t >= 1024 * 128) return;
    float x = w[t];
    __nv_bfloat16 hi = __float2bfloat16(x);
    __nv_bfloat16 lo = __float2bfloat16(x - __bfloat162float(hi));
    g_Wbf[t] = hi;
    g_Wbf[1024 * 128 + t] = lo;
}

// ---------------- qw[r] = w[r] @ q ; kw[r] = w[r] @ k ----------------
__global__ void qk_kernel(const float* __restrict__ w,
                          const float* __restrict__ q,
                          const float* __restrict__ k) {
    int r = blockIdx.x >> 1;
    int isK = blockIdx.x & 1;
    int i = threadIdx.x;
    const float4* wr = (const float4*)(w + (((size_t)r * 128 + i) << 7));
    const float4* v  = (const float4*)(isK ? k : q);
    float acc = 0.f;
#pragma unroll
    for (int o = 0; o < 32; ++o) {
        float4 a = wr[o], b = v[o];
        acc += a.x * b.x + a.y * b.y + a.z * b.z + a.w * b.w;
    }
    if (isK) g_kw[r * 128 + i] = acc;
    else     g_qw[r * 128 + i] = acc;
}

// ---------------- per-node-per-rel logit halves ----------------
__global__ void s_kernel(int layer) {
    int t = blockIdx.x * blockDim.x + threadIdx.x;
    if (t >= N_NODES * 16) return;
    int n = t >> 4;
    int rw = t & 15;
    int r = rw >> 1;
    int isK = rw & 1;
    const float* hin = (layer == 0) ? g_h : g_h2;
    const float4* hv = (const float4*)(hin + (size_t)n * 128);
    const float4* wv = (const float4*)((isK ? g_kw : g_qw) + r * 128);
    float acc = 0.f;
#pragma unroll
    for (int i = 0; i < 32; ++i) {
        float4 a = hv[i], b = wv[i];
        acc += a.x * b.x + a.y * b.y + a.z * b.z + a.w * b.w;
    }
    if (isK) g_sk[n * 8 + r] = acc;
    else     g_sq[n * 8 + r] = acc;
}

// ---------------- edge logits (sorted positions, sequential) ----------------
__global__ void alpha_kernel() {
    int j = blockIdx.x * blockDim.x + threadIdx.x;
    if (j >= N_EDGES) return;
    int dr = g_dr[j];
    int sn = g_srcs[j];
    float a = g_sq[dr] + g_sk[sn * 8 + (dr & 7)];
    g_alpha[j] = (a > 0.f) ? a : 0.2f * a;
}

// ---------------- warp-per-node softmax + aggregate -> Zbf bf16 hi/lo ----------------
__global__ __launch_bounds__(128) void aggregate_kernel(int layer) {
    const float* __restrict__ hin = (layer == 0) ? g_h : g_h2;
    int n = blockIdx.x * 4 + (threadIdx.x >> 5);
    if (n >= N_NODES) return;
    int lane = threadIdx.x & 31;
    int n8 = n * 8;
    int s = g_off8[n8], e = g_off8[n8 + 8];

    // segment max (whole dst neighborhood)
    float mx = -1e30f;
    for (int j = s + lane; j < e; j += 32) mx = fmaxf(mx, __ldg(g_alpha + j));
#pragma unroll
    for (int o = 16; o; o >>= 1) mx = fmaxf(mx, __shfl_xor_sync(0xffffffffu, mx, o));
    // denominator
    float den = 0.f;
    for (int j = s + lane; j < e; j += 32) den += __expf(__ldg(g_alpha + j) - mx);
#pragma unroll
    for (int o = 16; o; o >>= 1) den += __shfl_xor_sync(0xffffffffu, den, o);
    float inv = 1.f / (den + 1e-16f);

    const float* hbase = hin + lane * 4;
    __nv_bfloat16* zr = g_Zbf + (size_t)n * 2048 + lane * 4;

    int a = s;
#pragma unroll
    for (int r = 0; r < 8; ++r) {
        int b = g_off8[n8 + r + 1];
        float4 acc = make_float4(0.f, 0.f, 0.f, 0.f);
        for (int j = a; j < b; ++j) {
            float ex = __expf(__ldg(g_alpha + j) - mx);
            int sn = __ldg(g_srcs + j);
            float4 hv = *(const float4*)(hbase + (size_t)sn * 128);
            acc.x += ex * hv.x; acc.y += ex * hv.y;
            acc.z += ex * hv.z; acc.w += ex * hv.w;
        }
        a = b;
        float4 v = make_float4(acc.x * inv, acc.y * inv, acc.z * inv, acc.w * inv);
        __nv_bfloat162 h01 = __float22bfloat162_rn(make_float2(v.x, v.y));
        __nv_bfloat162 h23 = __float22bfloat162_rn(make_float2(v.z, v.w));
        float lx = v.x - __bfloat162float(h01.x);
        float ly = v.y - __bfloat162float(h01.y);
        float lz = v.z - __bfloat162float(h23.x);
        float lw = v.w - __bfloat162float(h23.y);
        __nv_bfloat162 l01 = __float22bfloat162_rn(make_float2(lx, ly));
        __nv_bfloat162 l23 = __float22bfloat162_rn(make_float2(lz, lw));
        union { __nv_bfloat162 b2[2]; uint2 u; } H, L;
        H.b2[0] = h01; H.b2[1] = h23;
        L.b2[0] = l01; L.b2[1] = l23;
        *(uint2*)(zr + r * 128) = H.u;
        *(uint2*)(zr + 1024 + r * 128) = L.u;
    }
}

// ================= mma.sync bf16 GEMM: out[M,128] = Z[M,1024] @ Wstack[1024,128] =================
__device__ __forceinline__ void stage_load(uint32_t st, int koff, int bm, int tid) {
#pragma unroll
    for (int it = 0; it < 4; ++it) {
        int i = tid + it * 256;
        int m = i >> 3, seg = i & 7;
        uint32_t sw = sw128((uint32_t)(m * 128 + seg * 16));
        const char* src = (const char*)(g_Zbf + (size_t)(bm + m) * 2048 + koff + seg * 8);
        CP16(st + sw, src);
        CP16(st + ST_ALO + sw, src + 2048);
    }
#pragma unroll
    for (int it = 0; it < 4; ++it) {
        int i = tid + it * 256;
        int k = i >> 4, nseg = i & 15;
        const char* src = (const char*)(g_Wbf + (size_t)(koff + k) * 128 + nseg * 8);
        CP16(st + ST_BHI + k * 272 + nseg * 16, src);
        CP16(st + ST_BLO + k * 272 + nseg * 16, src + 1024 * 128 * 2);
    }
}

__global__ __launch_bounds__(256, 1) void gemm_mma_kernel(float* __restrict__ out_ext,
                                                          const float* __restrict__ bias,
                                                          int relu, int to_h2) {
    extern __shared__ char sm[];
    uint32_t sb = smem_u32(sm);
    const int tid = threadIdx.x;
    const int wid = tid >> 5, lane = tid & 31;
    const int bm = blockIdx.x * 128;
    const int wm = wid & 3, wn = wid >> 2;

    float acc[2][8][4];
#pragma unroll
    for (int i = 0; i < 2; ++i)
#pragma unroll
        for (int j = 0; j < 8; ++j)
#pragma unroll
            for (int l = 0; l < 4; ++l) acc[i][j][l] = 0.f;

#pragma unroll
    for (int p = 0; p < 3; ++p) {
        stage_load(sb + p * STAGE_BYTES, p * 64, bm, tid);
        CP_COMMIT();
    }

    const int rA = lane & 15, cA = lane >> 4;
    const int rB8 = (lane & 7) + ((lane >> 3) & 1) * 8;
    const int nB = wn * 64 + (lane >> 4) * 8;

    for (int c = 0; c < 16; ++c) {
        CP_WAIT2();
        __syncthreads();
        uint32_t st = sb + (uint32_t)(c % 3) * STAGE_BYTES;

#pragma unroll
        for (int k16 = 0; k16 < 4; ++k16) {
            uint32_t aHi[2][4], aLo[2][4], bHi[8][2], bLo[8][2];
#pragma unroll
            for (int mt = 0; mt < 2; ++mt) {
                uint32_t sw = sw128((uint32_t)((wm * 32 + mt * 16 + rA) * 128 + k16 * 32 + cA * 16));
                LDSM_X4(aHi[mt], st + sw);
                LDSM_X4(aLo[mt], st + ST_ALO + sw);
            }
#pragma unroll
            for (int p = 0; p < 4; ++p) {
                uint32_t boff = (uint32_t)((k16 * 16 + rB8) * 272 + (nB + p * 16) * 2);
                LDSM_X4_T(bHi[2 * p][0], bHi[2 * p][1], bHi[2 * p + 1][0], bHi[2 * p + 1][1],
                          st + ST_BHI + boff);
                LDSM_X4_T(bLo[2 * p][0], bLo[2 * p][1], bLo[2 * p + 1][0], bLo[2 * p + 1][1],
                          st + ST_BLO + boff);
            }
#pragma unroll
            for (int mt = 0; mt < 2; ++mt)
#pragma unroll
                for (int nt = 0; nt < 8; ++nt) MMA_BF16(acc[mt][nt], aHi[mt], bHi[nt]);
#pragma unroll
            for (int mt = 0; mt < 2; ++mt)
#pragma unroll
                for (int nt = 0; nt < 8; ++nt) MMA_BF16(acc[mt][nt], aLo[mt], bHi[nt]);
#pragma unroll
            for (int mt = 0; mt < 2; ++mt)
#pragma unroll
                for (int nt = 0; nt < 8; ++nt) MMA_BF16(acc[mt][nt], aHi[mt], bLo[nt]);
        }
        __syncthreads();
        if (c + 3 < 16) stage_load(st, (c + 3) * 64, bm, tid);
        CP_COMMIT();
    }

    float* __restrict__ outp = to_h2 ? g_h2 : out_ext;
    const int g = lane >> 2, t4 = lane & 3;
#pragma unroll
    for (int mt = 0; mt < 2; ++mt) {
        int row0 = bm + wm * 32 + mt * 16 + g;
        int row1 = row0 + 8;
#pragma unroll
        for (int nt = 0; nt < 8; ++nt) {
            int col = wn * 64 + nt * 8 + t4 * 2;
            float b0 = __ldg(bias + col), b1 = __ldg(bias + col + 1);
            float v00 = acc[mt][nt][0] + b0, v01 = acc[mt][nt][1] + b1;
            float v10 = acc[mt][nt][2] + b0, v11 = acc[mt][nt][3] + b1;
            if (relu) {
                v00 = fmaxf(v00, 0.f); v01 = fmaxf(v01, 0.f);
                v10 = fmaxf(v10, 0.f); v11 = fmaxf(v11, 0.f);
            }
            if (row0 < N_NODES) *(float2*)(outp + (size_t)row0 * 128 + col) = make_float2(v00, v01);
            if (row1 < N_NODES) *(float2*)(outp + (size_t)row1 * 128 + col) = make_float2(v10, v11);
        }
    }
}

// ---------------- launch ----------------
extern "C" void kernel_launch(void* const* d_in, const int* in_sizes, int n_in,
                              void* d_out, int out_size) {
    const float* z     = (const float*)d_in[0];
    const float* lin_w = (const float*)d_in[1];
    const float* lin_b = (const float*)d_in[2];
    const float* w1    = (const float*)d_in[3];
    const float* q1    = (const float*)d_in[4];
    const float* k1    = (const float*)d_in[5];
    const float* b1    = (const float*)d_in[6];
    const float* w2    = (const float*)d_in[7];
    const float* q2    = (const float*)d_in[8];
    const float* k2    = (const float*)d_in[9];
    const float* b2    = (const float*)d_in[10];
    const int*   ei    = (const int*)d_in[11];
    const int*   et    = (const int*)d_in[12];
    const int* src = ei;
    const int* dst = ei + N_EDGES;
    float* out = (float*)d_out;

    cudaFuncSetAttribute(gemm_mma_kernel, cudaFuncAttributeMaxDynamicSharedMemorySize, GEMM_SMEM);

    const int EB = N_EDGES / 256;   // 3125

    // shared prep
    lin_kernel<<<(N_NODES * 128) / 256, 256>>>(z, lin_w, lin_b);
    zero8_kernel<<<(NBIN + 1023) / 1024, 1024>>>();
    hist8_kernel<<<EB, 256>>>(dst, et);
    scan1_kernel<<<SCAN_NB, 1024>>>();
    scan2_kernel<<<1, 512>>>();
    scan3_kernel<<<SCAN_NB, 1024>>>();
    scatter_kernel<<<EB, 256>>>(src, dst, et);

    // ---- layer 1 ----
    qk_kernel<<<16, 128>>>(w1, q1, k1);
    s_kernel<<<(N_NODES * 16) / 256, 256>>>(0);
    alpha_kernel<<<EB, 256>>>();
    splitW_kernel<<<512, 256>>>(w1);
    aggregate_kernel<<<(N_NODES + 3) / 4, 128>>>(0);
    gemm_mma_kernel<<<N_PAD / 128, 256, GEMM_SMEM>>>(out, b1, 1, 1);  // -> g_h2 (relu)

    // ---- layer 2 ----
    qk_kernel<<<16, 128>>>(w2, q2, k2);
    s_kernel<<<(N_NODES * 16) / 256, 256>>>(1);
    alpha_kernel<<<EB, 256>>>();
    splitW_kernel<<<512, 256>>>(w2);
    aggregate_kernel<<<(N_NODES + 3) / 4, 128>>>(1);
    gemm_mma_kernel<<<N_PAD / 128, 256, GEMM_SMEM>>>(out, b2, 0, 0);  // -> d_out
}